// round 5
// baseline (speedup 1.0000x reference)
#include <cuda_runtime.h>

#define NBLK 128
#define NTHR 512
#define BB   128
#define TT   512
#define PREDN 24
#define FF   16
#define LL   8
#define HH   1024
#define FROWS (TT + PREDN - 1)
#define KT   32

typedef unsigned long long ull;

// Persistent device scratch
__device__ float g_h0[2][BB * HH];
__device__ float g_h1[2][BB * HH];
__device__ float g_p[BB * LL];
__device__ unsigned g_count = 0;
__device__ unsigned g_gen = 0;

// ---------------- grid-wide sense-reversing barrier -------------------------
__device__ __forceinline__ void gbar() {
    __syncthreads();
    if (threadIdx.x == 0) {
        __threadfence();
        volatile unsigned* vg = &g_gen;
        unsigned g = *vg;
        if (atomicAdd(&g_count, 1u) == NBLK - 1) {
            g_count = 0;
            __threadfence();
            *vg = g + 1;
        } else {
            while (*vg == g) {}
        }
        __threadfence();
    }
    __syncthreads();
}

// group barrier: 256 threads, named barrier kh+1
__device__ __forceinline__ void barg(int kh) {
    asm volatile("bar.sync %0, 256;" :: "r"(kh + 1) : "memory");
}

// ---------------- GEMM slice with f32x2 packed FMA --------------------------
// Group of 256 threads computes C[128 b][24 cols] over k range
// [kbase, kbase + ntiles*KT). Thread (tu,tb) accumulates 4 consecutive b rows
// (pairs b01/b23 packed in f32x2) x 3 gate columns.
__device__ __forceinline__ void gemm_part(
    const float* __restrict__ hsrc, const float* __restrict__ W,
    int kbase, int ntiles, int u0, int tu, int tb, int kh, int t,
    ull a01[3], ull a23[3],
    float* __restrict__ shh,   // [KT][128]
    float* __restrict__ shw)   // [KT][24][2]  (weights duplicated)
{
    const int s = t & 255;
    // h staging role: b = s&127, k half = (s>>7)*16
    const int hb = s & 127;
    const int hhalf = (s >> 7) << 4;
    const float* hrow = hsrc + (long)hb * HH + kbase + hhalf;
    // w staging role: first 192 threads
    const bool wact = (s < 192);
    const int wcol = s >> 3;            // 0..23
    const int wk4 = (s & 7) << 2;       // 0..28
    const float* wrow = W;
    if (wact)
        wrow = W + (long)((wcol >> 3) * HH + u0 + (wcol & 7)) * HH + kbase + wk4;

    float4 h0v, h1v, h2v, h3v, wv;
    {   // prefetch tile 0
        const float4* hp = reinterpret_cast<const float4*>(hrow);
        h0v = __ldcg(hp); h1v = __ldcg(hp + 1); h2v = __ldcg(hp + 2); h3v = __ldcg(hp + 3);
        if (wact) wv = __ldg(reinterpret_cast<const float4*>(wrow));
    }

    const float* hcomp = shh + 4 * tb;
    const float* wcomp = shw + 2 * tu;

    for (int tile = 0; tile < ntiles; tile++) {
        barg(kh);   // buffer free (prev compute done in this group)
        // transposed h stage: shh[k][b]
        shh[(hhalf + 0) * 128 + hb] = h0v.x; shh[(hhalf + 1) * 128 + hb] = h0v.y;
        shh[(hhalf + 2) * 128 + hb] = h0v.z; shh[(hhalf + 3) * 128 + hb] = h0v.w;
        shh[(hhalf + 4) * 128 + hb] = h1v.x; shh[(hhalf + 5) * 128 + hb] = h1v.y;
        shh[(hhalf + 6) * 128 + hb] = h1v.z; shh[(hhalf + 7) * 128 + hb] = h1v.w;
        shh[(hhalf + 8) * 128 + hb] = h2v.x; shh[(hhalf + 9) * 128 + hb] = h2v.y;
        shh[(hhalf + 10) * 128 + hb] = h2v.z; shh[(hhalf + 11) * 128 + hb] = h2v.w;
        shh[(hhalf + 12) * 128 + hb] = h3v.x; shh[(hhalf + 13) * 128 + hb] = h3v.y;
        shh[(hhalf + 14) * 128 + hb] = h3v.z; shh[(hhalf + 15) * 128 + hb] = h3v.w;
        if (wact) {
            float2* wp = reinterpret_cast<float2*>(shw);
            wp[(wk4 + 0) * 24 + wcol] = make_float2(wv.x, wv.x);
            wp[(wk4 + 1) * 24 + wcol] = make_float2(wv.y, wv.y);
            wp[(wk4 + 2) * 24 + wcol] = make_float2(wv.z, wv.z);
            wp[(wk4 + 3) * 24 + wcol] = make_float2(wv.w, wv.w);
        }
        barg(kh);   // staged data visible

        if (tile + 1 < ntiles) {   // prefetch next tile into regs
            const float4* hp = reinterpret_cast<const float4*>(hrow + (tile + 1) * KT);
            h0v = __ldcg(hp); h1v = __ldcg(hp + 1); h2v = __ldcg(hp + 2); h3v = __ldcg(hp + 3);
            if (wact) wv = __ldg(reinterpret_cast<const float4*>(wrow + (tile + 1) * KT));
        }

        #pragma unroll
        for (int kk = 0; kk < KT; kk++) {
            ulonglong2 hp2 = *reinterpret_cast<const ulonglong2*>(hcomp + kk * 128);
            #pragma unroll
            for (int g = 0; g < 3; g++) {
                ull wpair = *reinterpret_cast<const ull*>(wcomp + kk * 48 + g * 16);
                asm("fma.rn.f32x2 %0, %1, %2, %0;" : "+l"(a01[g]) : "l"(hp2.x), "l"(wpair));
                asm("fma.rn.f32x2 %0, %1, %2, %0;" : "+l"(a23[g]) : "l"(hp2.y), "l"(wpair));
            }
        }
    }
}

// ---------------- partial exchange: kh1 -> kh0 ------------------------------
__device__ __forceinline__ void xfer(int t, int kh,
                                     const ull a01[3], const ull a23[3],
                                     float oth[3][4], float* __restrict__ red) {
    __syncthreads();
    if (kh == 1) {
        float2* rp = reinterpret_cast<float2*>(red) + (t & 255) * 6;
        rp[0] = *reinterpret_cast<const float2*>(&a01[0]);
        rp[1] = *reinterpret_cast<const float2*>(&a23[0]);
        rp[2] = *reinterpret_cast<const float2*>(&a01[1]);
        rp[3] = *reinterpret_cast<const float2*>(&a23[1]);
        rp[4] = *reinterpret_cast<const float2*>(&a01[2]);
        rp[5] = *reinterpret_cast<const float2*>(&a23[2]);
    }
    __syncthreads();
    if (kh == 0) {
        const float2* rp = reinterpret_cast<const float2*>(red) + t * 6;
        #pragma unroll
        for (int g = 0; g < 3; g++) {
            float2 p = rp[2 * g], q = rp[2 * g + 1];
            oth[g][0] = p.x; oth[g][1] = p.y; oth[g][2] = q.x; oth[g][3] = q.y;
        }
    }
}

__device__ __forceinline__ void unpack(const ull a01[3], const ull a23[3], float o[3][4]) {
    #pragma unroll
    for (int g = 0; g < 3; g++) {
        float2 p = *reinterpret_cast<const float2*>(&a01[g]);
        float2 q = *reinterpret_cast<const float2*>(&a23[g]);
        o[g][0] = p.x; o[g][1] = p.y; o[g][2] = q.x; o[g][3] = q.y;
    }
}

// ---------------- small input projection (K = 24) ---------------------------
__device__ __forceinline__ void load_wi_slice(const float* __restrict__ Wih, int u0,
                                              float* __restrict__ sh_wi) {
    for (int idx = threadIdx.x; idx < 24 * 24; idx += NTHR) {
        int jl = idx / 24, k = idx % 24;
        int g = jl >> 3, uu = jl & 7;
        sh_wi[k * 24 + jl] = Wih[(long)(g * HH + u0 + uu) * 24 + k];
    }
}

__device__ __forceinline__ void input_acc24(const float* __restrict__ sh_x,
                                            const float* __restrict__ sh_wi,
                                            int tu, int b0, float ai[3][4]) {
    #pragma unroll
    for (int g = 0; g < 3; g++)
        #pragma unroll
        for (int i = 0; i < 4; i++) ai[g][i] = 0.f;
    #pragma unroll
    for (int k = 0; k < 24; k++) {
        float w0 = sh_wi[k * 24 + tu];
        float w1 = sh_wi[k * 24 + 8 + tu];
        float w2 = sh_wi[k * 24 + 16 + tu];
        #pragma unroll
        for (int i = 0; i < 4; i++) {
            float xv = sh_x[(b0 + i) * 25 + k];
            ai[0][i] += xv * w0; ai[1][i] += xv * w1; ai[2][i] += xv * w2;
        }
    }
}

// ---------------- GRU pointwise update --------------------------------------
__device__ __forceinline__ void gru_update(const float ai[3][4], const float ah[3][4],
                                           const float* __restrict__ bih,
                                           const float* __restrict__ bhh,
                                           int jcol, int b0,
                                           const float* __restrict__ hcur,
                                           float* __restrict__ hnxt) {
    float bir = bih[jcol], biz = bih[HH + jcol], bin = bih[2 * HH + jcol];
    float bhr = bhh[jcol], bhz = bhh[HH + jcol], bhn = bhh[2 * HH + jcol];
    #pragma unroll
    for (int i = 0; i < 4; i++) {
        int b = b0 + i;
        float r = 1.f / (1.f + __expf(-(ai[0][i] + bir + ah[0][i] + bhr)));
        float z = 1.f / (1.f + __expf(-(ai[1][i] + biz + ah[1][i] + bhz)));
        float n = tanhf(ai[2][i] + bin + r * (ah[2][i] + bhn));
        float ho = __ldcg(hcur + (long)b * HH + jcol);
        __stcg(hnxt + (long)b * HH + jcol, (1.f - z) * n + z * ho);
    }
}

// ---------------- FC head ----------------------------------------------------
__device__ __forceinline__ void fc_phase(const float* __restrict__ h,
                                         const float* __restrict__ fcW,
                                         const float* __restrict__ fcb,
                                         float* __restrict__ outp) {
    int b = blockIdx.x;
    int w = threadIdx.x >> 5;
    int lane = threadIdx.x & 31;
    float s = 0.f;
    #pragma unroll
    for (int c = 0; c < 32; c++)
        s += __ldcg(h + (long)b * HH + 32 * c + lane) * fcW[(long)w * HH + 32 * c + lane];
    #pragma unroll
    for (int o = 16; o; o >>= 1) s += __shfl_down_sync(0xffffffffu, s, o);
    if (lane == 0) {
        float v = s + fcb[w];
        outp[b * LL + w] = v;
        __stcg(g_p + b * LL + w, v);
    }
}

// ---------------- persistent kernel -----------------------------------------
__global__ void __launch_bounds__(NTHR, 1) gru_persistent(
    const float* __restrict__ feats, const float* __restrict__ labels,
    const float* __restrict__ y, const int* __restrict__ teacher,
    const float* __restrict__ eWih0, const float* __restrict__ eWhh0,
    const float* __restrict__ ebih0, const float* __restrict__ ebhh0,
    const float* __restrict__ eWih1, const float* __restrict__ eWhh1,
    const float* __restrict__ ebih1, const float* __restrict__ ebhh1,
    const float* __restrict__ dWih, const float* __restrict__ dWhh,
    const float* __restrict__ dbih, const float* __restrict__ dbhh,
    const float* __restrict__ fcW, const float* __restrict__ fcb,
    float* __restrict__ out)
{
    // shared pool (46.25 KB), manually unioned:
    //   [0    .. 8192)  sh_h[2][KT][128]   (sh_x 3200 floats overlaps group0 tile)
    //   [8192 .. 11264) sh_w[2][KT*48]     (red 3072 floats overlaps)
    //   [11264.. 11840) sh_wi 576 floats
    __shared__ __align__(16) float smem[11840];
    float* sh_h  = smem;
    float* sh_w  = smem + 8192;
    float* sh_x  = smem;
    float* red   = smem + 8192;
    float* sh_wi = smem + 11264;

    const int t  = threadIdx.x;
    const int tu = t & 7;
    const int tb = (t >> 3) & 31;
    const int kh = t >> 8;
    const int b0 = tb * 4;
    const int u0 = blockIdx.x * 8;
    const int jcol = u0 + tu;
    const int teach = teacher[0];
    float* shh = sh_h + kh * (KT * 128);
    float* shw = sh_w + kh * (KT * 48);

    for (int i = blockIdx.x * NTHR + t; i < BB * HH; i += NBLK * NTHR) {
        g_h0[0][i] = 0.f;
        g_h1[0][i] = 0.f;
    }
    load_wi_slice(eWih0, u0, sh_wi);
    gbar();

    int cur = 0;
    // ================= encoder ==============================================
    for (int step = 0; step < TT; step++) {
        for (int idx = t; idx < BB * 24; idx += NTHR) {
            int b = idx / 24, k = idx % 24;
            float v = (k < FF) ? feats[((long)b * FROWS + step) * FF + k]
                               : labels[((long)b * TT + step) * LL + (k - FF)];
            sh_x[b * 25 + k] = v;
        }
        __syncthreads();

        // layer 0: split-K recurrent GEMM (+ tiny input projection on kh0)
        float ai[3][4];
        if (kh == 0) input_acc24(sh_x, sh_wi, tu, b0, ai);
        ull a01[3] = {0, 0, 0}, a23[3] = {0, 0, 0};
        gemm_part(g_h0[cur], eWhh0, kh * 512, 16, u0, tu, tb, kh, t, a01, a23, shh, shw);
        float oth[3][4];
        xfer(t, kh, a01, a23, oth, red);
        if (kh == 0) {
            float own[3][4], ah[3][4];
            unpack(a01, a23, own);
            #pragma unroll
            for (int g = 0; g < 3; g++)
                #pragma unroll
                for (int i = 0; i < 4; i++) ah[g][i] = own[g][i] + oth[g][i];
            gru_update(ai, ah, ebih0, ebhh0, jcol, b0, g_h0[cur], g_h0[cur ^ 1]);
        }
        gbar();

        // layer 1: dual GEMM (kh0 = Wih1 @ h0_next, kh1 = Whh1 @ h1_cur)
        a01[0] = a01[1] = a01[2] = 0; a23[0] = a23[1] = a23[2] = 0;
        gemm_part(kh ? g_h1[cur] : g_h0[cur ^ 1], kh ? eWhh1 : eWih1,
                  0, 32, u0, tu, tb, kh, t, a01, a23, shh, shw);
        xfer(t, kh, a01, a23, oth, red);
        if (kh == 0) {
            float gi[3][4];
            unpack(a01, a23, gi);
            gru_update(gi, oth, ebih1, ebhh1, jcol, b0, g_h1[cur], g_h1[cur ^ 1]);
        }
        gbar();
        cur ^= 1;
    }

    if (t < 256) fc_phase(g_h1[cur], fcW, fcb, out);
    load_wi_slice(dWih, u0, sh_wi);
    gbar();

    // ================= decoder ==============================================
    for (int s = 0; s < PREDN - 1; s++) {
        for (int idx = t; idx < BB * 24; idx += NTHR) {
            int b = idx / 24, k = idx % 24;
            float v;
            if (k < FF)      v = feats[((long)b * FROWS + TT + s) * FF + k];
            else if (teach)  v = y[((long)b * (PREDN - 1) + s) * LL + (k - FF)];
            else             v = __ldcg(g_p + b * LL + (k - FF));
            sh_x[b * 25 + k] = v;
        }
        __syncthreads();

        float ai[3][4];
        if (kh == 0) input_acc24(sh_x, sh_wi, tu, b0, ai);
        ull a01[3] = {0, 0, 0}, a23[3] = {0, 0, 0};
        gemm_part(g_h1[cur], dWhh, kh * 512, 16, u0, tu, tb, kh, t, a01, a23, shh, shw);
        float oth[3][4];
        xfer(t, kh, a01, a23, oth, red);
        if (kh == 0) {
            float own[3][4], ah[3][4];
            unpack(a01, a23, own);
            #pragma unroll
            for (int g = 0; g < 3; g++)
                #pragma unroll
                for (int i = 0; i < 4; i++) ah[g][i] = own[g][i] + oth[g][i];
            gru_update(ai, ah, dbih, dbhh, jcol, b0, g_h1[cur], g_h1[cur ^ 1]);
        }
        gbar();

        if (t < 256) fc_phase(g_h1[cur ^ 1], fcW, fcb, out + (long)(s + 1) * BB * LL);
        gbar();
        cur ^= 1;
    }
}

extern "C" void kernel_launch(void* const* d_in, const int* in_sizes, int n_in,
                              void* d_out, int out_size) {
    const float* feats  = (const float*)d_in[0];
    const float* labels = (const float*)d_in[1];
    const float* y      = (const float*)d_in[2];
    const int*   teach  = (const int*)d_in[3];
    const float* eWih0  = (const float*)d_in[4];
    const float* eWhh0  = (const float*)d_in[5];
    const float* ebih0  = (const float*)d_in[6];
    const float* ebhh0  = (const float*)d_in[7];
    const float* eWih1  = (const float*)d_in[8];
    const float* eWhh1  = (const float*)d_in[9];
    const float* ebih1  = (const float*)d_in[10];
    const float* ebhh1  = (const float*)d_in[11];
    const float* dWih   = (const float*)d_in[12];
    const float* dWhh   = (const float*)d_in[13];
    const float* dbih   = (const float*)d_in[14];
    const float* dbhh   = (const float*)d_in[15];
    const float* fcW    = (const float*)d_in[16];
    const float* fcb    = (const float*)d_in[17];
    float* out = (float*)d_out;

    gru_persistent<<<NBLK, NTHR>>>(feats, labels, y, teach,
                                   eWih0, eWhh0, ebih0, ebhh0,
                                   eWih1, eWhh1, ebih1, ebhh1,
                                   dWih, dWhh, dbih, dbhh,
                                   fcW, fcb, out);
}

// round 6
// speedup vs baseline: 5.2935x; 5.2935x over previous
#include <cuda_runtime.h>
#include <cuda_bf16.h>

#define NBLK 128
#define NTHR 256
#define BB   128
#define TT   512
#define PREDN 24
#define FF   16
#define LL   8
#define HH   1024
#define FROWS (TT + PREDN - 1)

typedef unsigned int uint;

// ---------------- persistent device scratch ---------------------------------
// A planes (hidden states) in MMA A-fragment order:
//   uint4 index = (rg*64 + kg)*32 + lane, rg = b>>4, kg = u>>4
//   within uint4: halves[ireg*2 + (u&1)], ireg = (r>=8) + 2*(u%16>=8),
//   lane = (b&7... see store_h/load_h for exact mapping.
__device__ uint4 g_A0[2][2][8 * 64 * 32];   // [buf][plane hi/lo][idx]  (1 MB)
__device__ uint4 g_A1[2][2][8 * 64 * 32];
// B (weights) pre-split + pre-permuted into per-thread fragment order:
// [mat][block][nw][hc][plane][lane], uint4 = {b0(kgl0), b1(kgl0), b0(kgl1), b1(kgl1)}
__device__ uint4 g_B[4][NBLK][3][32][2][32];  // 50.3 MB
__device__ float g_p[BB * LL];
__device__ unsigned g_count = 0;
__device__ unsigned g_gen = 0;

// ---------------- grid barrier ----------------------------------------------
__device__ __forceinline__ void gbar() {
    __syncthreads();
    if (threadIdx.x == 0) {
        __threadfence();
        volatile unsigned* vg = &g_gen;
        unsigned g = *vg;
        if (atomicAdd(&g_count, 1u) == NBLK - 1) {
            g_count = 0;
            __threadfence();
            *vg = g + 1;
        } else {
            while (*vg == g) {}
        }
        __threadfence();
    }
    __syncthreads();
}

// ---------------- 2B coherent global ld/st ----------------------------------
__device__ __forceinline__ unsigned short ldcg_u16(const void* p) {
    unsigned short v;
    asm volatile("ld.global.cg.u16 %0, [%1];" : "=h"(v) : "l"(p));
    return v;
}
__device__ __forceinline__ void stcg_u16(void* p, unsigned short v) {
    asm volatile("st.global.cg.u16 [%0], %1;" :: "l"(p), "h"(v));
}

// ---------------- h element <-> fragment-layout mapping ----------------------
__device__ __forceinline__ long h_off(int b, int u) {
    int rg = b >> 4, r = b & 15, kp = u & 15, kg = u >> 4;
    int ireg = (r >> 3) + ((kp >> 3) << 1);
    int ln = (r & 7) * 4 + ((kp & 7) >> 1);
    return ((long)((rg * 64 + kg) * 32 + ln)) * 16 + ireg * 4 + (kp & 1) * 2;
}
__device__ __forceinline__ void store_h(uint4* Ph, uint4* Pl, int b, int u, float v) {
    __nv_bfloat16 hi = __float2bfloat16(v);
    __nv_bfloat16 lo = __float2bfloat16(v - __bfloat162float(hi));
    long off = h_off(b, u);
    stcg_u16((char*)Ph + off, __bfloat16_as_ushort(hi));
    stcg_u16((char*)Pl + off, __bfloat16_as_ushort(lo));
}
__device__ __forceinline__ float load_h(const uint4* Ph, const uint4* Pl, int b, int u) {
    long off = h_off(b, u);
    float hi = __bfloat162float(__ushort_as_bfloat16(ldcg_u16((const char*)Ph + off)));
    float lo = __bfloat162float(__ushort_as_bfloat16(ldcg_u16((const char*)Pl + off)));
    return hi + lo;
}

// ---------------- HMMA m16n8k16 bf16 -> f32 ----------------------------------
__device__ __forceinline__ void mma16816(float* c, const uint* a, uint b0, uint b1) {
    asm volatile(
        "mma.sync.aligned.m16n8k16.row.col.f32.bf16.bf16.f32 "
        "{%0,%1,%2,%3}, {%4,%5,%6,%7}, {%8,%9}, {%0,%1,%2,%3};"
        : "+f"(c[0]), "+f"(c[1]), "+f"(c[2]), "+f"(c[3])
        : "r"(a[0]), "r"(a[1]), "r"(a[2]), "r"(a[3]), "r"(b0), "r"(b1));
}

struct FragHC {
    uint4 ah[2], al[2];   // A hi/lo, [kgl]
    uint4 bh[3], bl[3];   // B hi/lo, [nf]
};

__device__ __forceinline__ void ld_hc(FragHC& f, const uint4* __restrict__ Ah,
                                      const uint4* __restrict__ Al,
                                      const uint4* __restrict__ B0,
                                      int w, int lane, int hc) {
    #pragma unroll
    for (int kgl = 0; kgl < 2; kgl++) {
        int ai = (w * 64 + hc * 2 + kgl) * 32 + lane;
        f.ah[kgl] = __ldcg(Ah + ai);
        f.al[kgl] = __ldcg(Al + ai);
    }
    #pragma unroll
    for (int nf = 0; nf < 3; nf++) {
        const uint4* bp = B0 + nf * 2048 + hc * 64 + lane;
        f.bh[nf] = __ldg(bp);
        f.bl[nf] = __ldg(bp + 32);
    }
}

__device__ __forceinline__ void do_hc(const FragHC& f, float acc[3][4]) {
    #pragma unroll
    for (int kgl = 0; kgl < 2; kgl++) {
        const uint* ah = (const uint*)&f.ah[kgl];
        const uint* al = (const uint*)&f.al[kgl];
        #pragma unroll
        for (int nf = 0; nf < 3; nf++) {
            uint bh0 = kgl ? f.bh[nf].z : f.bh[nf].x;
            uint bh1 = kgl ? f.bh[nf].w : f.bh[nf].y;
            uint bl0 = kgl ? f.bl[nf].z : f.bl[nf].x;
            uint bl1 = kgl ? f.bl[nf].w : f.bl[nf].y;
            mma16816(acc[nf], ah, bh0, bh1);   // hi*hi
            mma16816(acc[nf], al, bh0, bh1);   // lo*hi
            mma16816(acc[nf], ah, bl0, bl1);   // hi*lo
        }
    }
}

// One full K=1024 GEMM slab: warp w owns batch rows [16w,16w+16), all 24 cols.
__device__ void gemm_mma(const uint4* __restrict__ Ah, const uint4* __restrict__ Al,
                         const uint4* __restrict__ B0, int w, int lane,
                         float acc[3][4]) {
    #pragma unroll
    for (int nf = 0; nf < 3; nf++)
        #pragma unroll
        for (int i = 0; i < 4; i++) acc[nf][i] = 0.f;
    FragHC f0, f1;
    ld_hc(f0, Ah, Al, B0, w, lane, 0);
    ld_hc(f1, Ah, Al, B0, w, lane, 1);
    #pragma unroll 1
    for (int hc = 0; hc < 32; hc += 2) {
        do_hc(f0, acc);
        if (hc + 2 < 32) ld_hc(f0, Ah, Al, B0, w, lane, hc + 2);
        do_hc(f1, acc);
        if (hc + 3 < 32) ld_hc(f1, Ah, Al, B0, w, lane, hc + 3);
    }
}

// C fragment -> smem buffer [24 cols][128 b]
__device__ __forceinline__ void epi(const float acc[3][4], float* __restrict__ buf,
                                    int w, int lane) {
    int row = lane >> 2, c2 = (lane & 3) * 2;
    int b = w * 16 + row;
    #pragma unroll
    for (int nf = 0; nf < 3; nf++) {
        int col = nf * 8 + c2;
        buf[col * 128 + b]           = acc[nf][0];
        buf[(col + 1) * 128 + b]     = acc[nf][1];
        buf[col * 128 + b + 8]       = acc[nf][2];
        buf[(col + 1) * 128 + b + 8] = acc[nf][3];
    }
}

// ---------------- small input projection (K = 24) ---------------------------
__device__ __forceinline__ void load_wi_slice(const float* __restrict__ Wih, int u0,
                                              float* __restrict__ sh_wi) {
    for (int idx = threadIdx.x; idx < 24 * 24; idx += NTHR) {
        int jl = idx / 24, k = idx % 24;
        int g = jl >> 3, uu = jl & 7;
        sh_wi[k * 24 + jl] = Wih[(long)(g * HH + u0 + uu) * 24 + k];
    }
}

__device__ __forceinline__ void input_acc24(const float* __restrict__ sh_x,
                                            const float* __restrict__ sh_wi,
                                            int tu, int b0, float ai[3][4]) {
    #pragma unroll
    for (int g = 0; g < 3; g++)
        #pragma unroll
        for (int i = 0; i < 4; i++) ai[g][i] = 0.f;
    #pragma unroll
    for (int k = 0; k < 24; k++) {
        float w0 = sh_wi[k * 24 + tu];
        float w1 = sh_wi[k * 24 + 8 + tu];
        float w2 = sh_wi[k * 24 + 16 + tu];
        #pragma unroll
        for (int i = 0; i < 4; i++) {
            float xv = sh_x[(b0 + i) * 25 + k];
            ai[0][i] += xv * w0; ai[1][i] += xv * w1; ai[2][i] += xv * w2;
        }
    }
}

// ---------------- GRU pointwise update --------------------------------------
__device__ __forceinline__ void gru_upd(const float ai[3][4], const float* __restrict__ s_gh,
                                        const float* __restrict__ bih,
                                        const float* __restrict__ bhh,
                                        int tu, int b0, int jcol,
                                        const uint4* Phc, const uint4* Plc,
                                        uint4* Phn, uint4* Pln) {
    float bir = bih[jcol], biz = bih[HH + jcol], bin = bih[2 * HH + jcol];
    float bhr = bhh[jcol], bhz = bhh[HH + jcol], bhn = bhh[2 * HH + jcol];
    #pragma unroll
    for (int i = 0; i < 4; i++) {
        int b = b0 + i;
        float ahr = s_gh[tu * 128 + b];
        float ahz = s_gh[(8 + tu) * 128 + b];
        float ahn = s_gh[(16 + tu) * 128 + b];
        float r = 1.f / (1.f + __expf(-(ai[0][i] + bir + ahr + bhr)));
        float z = 1.f / (1.f + __expf(-(ai[1][i] + biz + ahz + bhz)));
        float n = tanhf(ai[2][i] + bin + r * (ahn + bhn));
        float ho = load_h(Phc, Plc, b, jcol);
        store_h(Phn, Pln, b, jcol, (1.f - z) * n + z * ho);
    }
}

// ---------------- FC head ----------------------------------------------------
__device__ __forceinline__ void fc_phase(const uint4* Ph, const uint4* Pl,
                                         const float* __restrict__ fcW,
                                         const float* __restrict__ fcb,
                                         float* __restrict__ outp) {
    int b = blockIdx.x;
    int w = threadIdx.x >> 5;
    int lane = threadIdx.x & 31;
    float s = 0.f;
    #pragma unroll
    for (int c = 0; c < 32; c++) {
        int u = c * 32 + lane;
        s += load_h(Ph, Pl, b, u) * fcW[(long)w * HH + u];
    }
    #pragma unroll
    for (int o = 16; o; o >>= 1) s += __shfl_down_sync(0xffffffffu, s, o);
    if (lane == 0) {
        float v = s + fcb[w];
        outp[b * LL + w] = v;
        asm volatile("st.global.cg.f32 [%0], %1;" :: "l"(g_p + b * LL + w), "f"(v));
    }
}

// ---------------- persistent kernel -----------------------------------------
__global__ void __launch_bounds__(NTHR, 1) gru_persistent(
    const float* __restrict__ feats, const float* __restrict__ labels,
    const float* __restrict__ y, const int* __restrict__ teacher,
    const float* __restrict__ eWih0, const float* __restrict__ eWhh0,
    const float* __restrict__ ebih0, const float* __restrict__ ebhh0,
    const float* __restrict__ eWih1, const float* __restrict__ eWhh1,
    const float* __restrict__ ebih1, const float* __restrict__ ebhh1,
    const float* __restrict__ dWih, const float* __restrict__ dWhh,
    const float* __restrict__ dbih, const float* __restrict__ dbhh,
    const float* __restrict__ fcW, const float* __restrict__ fcb,
    float* __restrict__ out)
{
    __shared__ float sh_x[BB * 25];
    __shared__ float sh_wi[24 * 24];
    __shared__ float s_gi[24 * 128];
    __shared__ float s_gh[24 * 128];

    const int t = threadIdx.x;
    const int w = t >> 5;
    const int lane = t & 31;
    const int tu = t & 7;
    const int tb = t >> 3;
    const int b0 = tb * 4;
    const int u0 = blockIdx.x * 8;
    const int jcol = u0 + tu;
    const int teach = teacher[0];

    // ---- zero h (buf 0, both planes) ----
    {
        uint4 z = make_uint4(0, 0, 0, 0);
        int gid = blockIdx.x * NTHR + t;              // NBLK*NTHR == 32768 exactly
        ((uint4*)g_A0)[gid] = z;
        ((uint4*)g_A1)[gid] = z;
    }

    // ---- split + permute weights into fragment order (per block slice) ----
    {
        const float* Wm[4] = {eWhh0, eWih1, eWhh1, dWhh};
        for (int wdx = t; wdx < 4 * 3 * 32 * 2 * 32; wdx += NTHR) {
            int ln = wdx & 31;
            int pl = (wdx >> 5) & 1;
            int hc = (wdx >> 6) & 31;
            int rest = wdx >> 11;
            int nw = rest % 3, m = rest / 3;
            const float* W = Wm[m];
            int u = ln >> 2;
            long wr = (long)(nw * HH + u0 + u) * HH;
            uint vals[4];
            #pragma unroll
            for (int c = 0; c < 4; c++) {
                int k0 = hc * 32 + (c >> 1) * 16 + (c & 1) * 8 + (ln & 3) * 2;
                float2 xv = *reinterpret_cast<const float2*>(W + wr + k0);
                __nv_bfloat16 h0 = __float2bfloat16(xv.x);
                __nv_bfloat16 h1 = __float2bfloat16(xv.y);
                if (pl) {
                    h0 = __float2bfloat16(xv.x - __bfloat162float(h0));
                    h1 = __float2bfloat16(xv.y - __bfloat162float(h1));
                }
                vals[c] = (uint)__bfloat16_as_ushort(h0) |
                          ((uint)__bfloat16_as_ushort(h1) << 16);
            }
            g_B[m][blockIdx.x][nw][hc][pl][ln] = make_uint4(vals[0], vals[1], vals[2], vals[3]);
        }
    }
    load_wi_slice(eWih0, u0, sh_wi);
    gbar();

    int cur = 0;
    float acc[3][4];

    // ================= encoder ==============================================
    for (int step = 0; step < TT; step++) {
        for (int idx = t; idx < BB * 24; idx += NTHR) {
            int b = idx / 24, k = idx % 24;
            float v = (k < FF) ? feats[((long)b * FROWS + step) * FF + k]
                               : labels[((long)b * TT + step) * LL + (k - FF)];
            sh_x[b * 25 + k] = v;
        }
        __syncthreads();

        // layer 0
        gemm_mma(g_A0[cur][0], g_A0[cur][1], &g_B[0][blockIdx.x][0][0][0][0], w, lane, acc);
        epi(acc, s_gh, w, lane);
        __syncthreads();
        {
            float ai[3][4];
            input_acc24(sh_x, sh_wi, tu, b0, ai);
            gru_upd(ai, s_gh, ebih0, ebhh0, tu, b0, jcol,
                    g_A0[cur][0], g_A0[cur][1], g_A0[cur ^ 1][0], g_A0[cur ^ 1][1]);
        }
        gbar();

        // layer 1: gi = Wih1 @ h0_new, gh = Whh1 @ h1_cur
        gemm_mma(g_A0[cur ^ 1][0], g_A0[cur ^ 1][1], &g_B[1][blockIdx.x][0][0][0][0], w, lane, acc);
        epi(acc, s_gi, w, lane);
        gemm_mma(g_A1[cur][0], g_A1[cur][1], &g_B[2][blockIdx.x][0][0][0][0], w, lane, acc);
        epi(acc, s_gh, w, lane);
        __syncthreads();
        {
            float gi[3][4];
            #pragma unroll
            for (int g = 0; g < 3; g++)
                #pragma unroll
                for (int i = 0; i < 4; i++) gi[g][i] = s_gi[(g * 8 + tu) * 128 + b0 + i];
            gru_upd(gi, s_gh, ebih1, ebhh1, tu, b0, jcol,
                    g_A1[cur][0], g_A1[cur][1], g_A1[cur ^ 1][0], g_A1[cur ^ 1][1]);
        }
        gbar();
        cur ^= 1;
    }

    // ps -> out[0] + seed g_p
    fc_phase(g_A1[cur][0], g_A1[cur][1], fcW, fcb, out);
    load_wi_slice(dWih, u0, sh_wi);
    gbar();

    // ================= decoder ==============================================
    for (int s = 0; s < PREDN - 1; s++) {
        for (int idx = t; idx < BB * 24; idx += NTHR) {
            int b = idx / 24, k = idx % 24;
            float v;
            if (k < FF)      v = feats[((long)b * FROWS + TT + s) * FF + k];
            else if (teach)  v = y[((long)b * (PREDN - 1) + s) * LL + (k - FF)];
            else             v = __ldcg(g_p + b * LL + (k - FF));
            sh_x[b * 25 + k] = v;
        }
        __syncthreads();

        gemm_mma(g_A1[cur][0], g_A1[cur][1], &g_B[3][blockIdx.x][0][0][0][0], w, lane, acc);
        epi(acc, s_gh, w, lane);
        __syncthreads();
        {
            float ai[3][4];
            input_acc24(sh_x, sh_wi, tu, b0, ai);
            gru_upd(ai, s_gh, dbih, dbhh, tu, b0, jcol,
                    g_A1[cur][0], g_A1[cur][1], g_A1[cur ^ 1][0], g_A1[cur ^ 1][1]);
        }
        gbar();

        fc_phase(g_A1[cur ^ 1][0], g_A1[cur ^ 1][1], fcW, fcb, out + (long)(s + 1) * BB * LL);
        gbar();
        cur ^= 1;
    }
}

extern "C" void kernel_launch(void* const* d_in, const int* in_sizes, int n_in,
                              void* d_out, int out_size) {
    const float* feats  = (const float*)d_in[0];
    const float* labels = (const float*)d_in[1];
    const float* y      = (const float*)d_in[2];
    const int*   teach  = (const int*)d_in[3];
    const float* eWih0  = (const float*)d_in[4];
    const float* eWhh0  = (const float*)d_in[5];
    const float* ebih0  = (const float*)d_in[6];
    const float* ebhh0  = (const float*)d_in[7];
    const float* eWih1  = (const float*)d_in[8];
    const float* eWhh1  = (const float*)d_in[9];
    const float* ebih1  = (const float*)d_in[10];
    const float* ebhh1  = (const float*)d_in[11];
    const float* dWih   = (const float*)d_in[12];
    const float* dWhh   = (const float*)d_in[13];
    const float* dbih   = (const float*)d_in[14];
    const float* dbhh   = (const float*)d_in[15];
    const float* fcW    = (const float*)d_in[16];
    const float* fcb    = (const float*)d_in[17];
    float* out = (float*)d_out;

    gru_persistent<<<NBLK, NTHR>>>(feats, labels, y, teach,
                                   eWih0, eWhh0, ebih0, ebhh0,
                                   eWih1, eWhh1, ebih1, ebhh1,
                                   dWih, dWhh, dbih, dbhh,
                                   fcW, fcb, out);
}